// round 16
// baseline (speedup 1.0000x reference)
#include <cuda_runtime.h>
#include <cuda_fp16.h>
#include <cstdint>
#include <math.h>

#define G_DIM   2304
#define HIDDEN  150
#define N_PAIRS 32768
#define N_MENT  4096
#define N_SEG   1024

#define TM 128
#define TN 160
#define SK 64                    // K per stage
#define NSUP (G_DIM / SK)        // 36
#define KSPLIT 4
#define NSUP_PRE (NSUP / KSPLIT) // 9

#define RPAD 36    // uint row stride (32 data + 4 pad), conflict-free

#define ABUFS 2
#define BBUFS 3                  // pair path uses 3; pre path uses bufs 0,1
#define AS_UINTS (ABUFS * TM * RPAD)       // 9216
#define BS_UINTS (BBUFS * TN * RPAD)       // 17280
#define DYN_BYTES ((AS_UINTS + BS_UINTS) * 4)   // 105984

// ---------------- device scratch (static; no allocation) -------------------
__device__ __half d_Gh[N_MENT * G_DIM];           // g_i in fp16
__device__ __half d_Wh[3 * TN * G_DIM];           // W1^T fp16 [sec][h][k]
__device__ float d_part[KSPLIT][2][N_MENT * TN];  // precompute partials
__device__ float d_Abuf[N_MENT * TN];
__device__ float d_Bbuf[N_MENT * TN];
__device__ float d_bias[3 * TN];
__device__ float d_scores[N_PAIRS];

__device__ __forceinline__ uint32_t smem_u32(const void* p) {
    uint32_t a;
    asm("{ .reg .u64 t; cvta.to.shared.u64 t, %1; cvt.u32.u64 %0, t; }"
        : "=r"(a) : "l"(p));
    return a;
}
__device__ __forceinline__ void cp_async16(uint32_t dst, const void* src) {
    asm volatile("cp.async.cg.shared.global [%0], [%1], 16;"
                 :: "r"(dst), "l"(src) : "memory");
}
#define CP_COMMIT() asm volatile("cp.async.commit_group;" ::: "memory")
#define CP_WAIT0()  asm volatile("cp.async.wait_group 0;" ::: "memory")
#define CP_WAIT1()  asm volatile("cp.async.wait_group 1;" ::: "memory")

__device__ __forceinline__ void mma_f16(float* d, const uint32_t* a,
                                        const uint32_t* b) {
    asm volatile(
        "mma.sync.aligned.m16n8k16.row.col.f32.f16.f16.f32 "
        "{%0,%1,%2,%3}, {%4,%5,%6,%7}, {%8,%9}, {%0,%1,%2,%3};"
        : "+f"(d[0]), "+f"(d[1]), "+f"(d[2]), "+f"(d[3])
        : "r"(a[0]), "r"(a[1]), "r"(a[2]), "r"(a[3]), "r"(b[0]), "r"(b[1]));
}
__device__ __forceinline__ void ldmatrix_x4(uint32_t* r, uint32_t addr) {
    asm volatile("ldmatrix.sync.aligned.m8n8.x4.shared.b16 {%0,%1,%2,%3}, [%4];"
                 : "=r"(r[0]), "=r"(r[1]), "=r"(r[2]), "=r"(r[3]) : "r"(addr));
}
__device__ __forceinline__ void ldmatrix_x2(uint32_t* r, uint32_t addr) {
    asm volatile("ldmatrix.sync.aligned.m8n8.x2.shared.b16 {%0,%1}, [%2];"
                 : "=r"(r[0]), "=r"(r[1]) : "r"(addr));
}

// ---------------------------------------------------------------------------
__global__ void prep_g_kernel(const float* __restrict__ G) {
    int idx = blockIdx.x * 256 + threadIdx.x;     // float4 units
    if (idx >= N_MENT * G_DIM / 4) return;
    float4 v = reinterpret_cast<const float4*>(G)[idx];
    __half2 h0 = __floats2half2_rn(v.x, v.y);
    __half2 h1 = __floats2half2_rn(v.z, v.w);
    uint2 u;
    u.x = *reinterpret_cast<uint32_t*>(&h0);
    u.y = *reinterpret_cast<uint32_t*>(&h1);
    reinterpret_cast<uint2*>(d_Gh)[idx] = u;
}

// ---------------------------------------------------------------------------
__global__ void prep_w_kernel(const float* __restrict__ W1) {
    __shared__ float t[32][33];
    const int k0 = blockIdx.x * 32, h0 = blockIdx.y * 32, sec = blockIdx.z;
    const int tx = threadIdx.x, ty = threadIdx.y;
    #pragma unroll
    for (int r = 0; r < 4; r++) {
        int ky = ty + r * 8, h = h0 + tx;
        t[ky][tx] = (h < HIDDEN)
            ? W1[(size_t)(sec * G_DIM + k0 + ky) * HIDDEN + h] : 0.f;
    }
    __syncthreads();
    #pragma unroll
    for (int r = 0; r < 4; r++) {
        int hy = ty + r * 8;
        d_Wh[(size_t)sec * TN * G_DIM + (size_t)(h0 + hy) * G_DIM + k0 + tx] =
            __float2half_rn(t[tx][hy]);
    }
}

// ---------------------------------------------------------------------------
__global__ void bias_kernel(const float* __restrict__ spk,
                            const float* __restrict__ W1,
                            const float* __restrict__ b1) {
    const float* Wd = W1 + (size_t)(3 * G_DIM) * HIDDEN;
    for (int idx = threadIdx.x; idx < 3 * TN; idx += blockDim.x) {
        int s = idx / TN, h = idx % TN;
        float v = 0.f;
        if (h < HIDDEN) {
            v = b1[h];
            #pragma unroll
            for (int t = 0; t < 20; t++)
                v = fmaf(spk[s * 20 + t], Wd[(size_t)t * HIDDEN + h], v);
        }
        d_bias[idx] = v;
    }
}

// ---------------------------------------------------------------------------
// fp16 mma.sync GEMM (m16n8k16), ldmatrix frags, SK=64 stages.
// 8 warps (2 M x 4 N), warp tile 64x40; one barrier per stage.
//   PAIR=true : B TRIPLE-buffered (staged 2 ahead, wait_group 1);
//               A = hmul2 gather double-buffered via STS.
//   PAIR=false: R12 scheme verbatim — A+B cp.async double-buffered, WAIT0.
// ---------------------------------------------------------------------------
template<bool PAIR>
__global__ __launch_bounds__(256, 2)
void mma_kernel(const int*   __restrict__ m_ids,
                const int*   __restrict__ a_ids,
                const int*   __restrict__ spk_lbl,
                const float* __restrict__ mscores,
                const float* __restrict__ W2,
                const float* __restrict__ b2,
                int nsup) {
    extern __shared__ uint32_t dynu[];
    uint32_t* Au = dynu;                 // [ABUFS][TM][RPAD]
    uint32_t* Bu = dynu + AS_UINTS;      // [BBUFS][TN][RPAD]
    __shared__ float srow[4][TM];
    __shared__ float bias_s[3 * TN];
    __shared__ float w2s[TN];

    const int tid = threadIdx.x;
    const int wid = tid >> 5, lane = tid & 31;
    const int gID = lane >> 2, tig = lane & 3;
    const int warp_m = wid & 1, warp_n = wid >> 1;
    const int base = blockIdx.x * TM;
    const int koff = PAIR ? 0 : blockIdx.z * NSUP_PRE * SK;

    if (PAIR) {
        if (tid < TN) w2s[tid] = (tid < HIDDEN) ? W2[tid] : 0.f;
        for (int i = tid; i < 3 * TN; i += 256) bias_s[i] = d_bias[i];
    }

    const __half* Wh = d_Wh + (size_t)(PAIR ? 2 : blockIdx.y) * TN * G_DIM;

    // A-gather roles: 8 threads/row, q = 16B slot (8 halfs); 4 row passes.
    const int rbase = tid >> 3;   // 0..31
    const int q = tid & 7;        // 0..7
    int idx_i[4], idx_j[4];
    if (PAIR) {
        #pragma unroll
        for (int p = 0; p < 4; p++) {
            const int r = base + rbase + 32 * p;
            idx_i[p] = m_ids[r];
            idx_j[p] = a_ids[r];
        }
    }

    float acc[4][5][4];
    #pragma unroll
    for (int a = 0; a < 4; a++)
        #pragma unroll
        for (int b = 0; b < 5; b++)
            #pragma unroll
            for (int c = 0; c < 4; c++) acc[a][b][c] = 0.f;

    const uint32_t au_base = smem_u32(Au);
    const uint32_t bs_base = smem_u32(Bu);

    const int a_rowsel = (lane & 7) + ((lane >> 3) & 1) * 8;
    const int a_ksel   = (lane >> 4) & 1;
    const uint32_t a_lane_off = au_base
        + 4u * ((uint32_t)a_rowsel * RPAD + (uint32_t)a_ksel * 4);
    const int b_colsel = lane & 7;
    const int b_ksel   = (lane >> 3) & 1;
    const uint32_t b_lane_off = bs_base
        + 4u * ((uint32_t)b_colsel * RPAD + (uint32_t)b_ksel * 4);

    auto stage_B = [&](int S, int buf) {
        #pragma unroll
        for (int it = 0; it < 5; it++) {
            int u = tid + it * 256;          // 1280 x 16B units
            int col = u >> 3, q4 = u & 7;
            const __half* src = Wh + (size_t)col * G_DIM + koff + S * SK + q4 * 8;
            cp_async16(bs_base + (uint32_t)((buf * TN + col) * RPAD + q4 * 4) * 4u,
                       src);
        }
    };
    auto stage_A_pre = [&](int S, int buf) {   // PRE only
        #pragma unroll
        for (int it = 0; it < 4; it++) {
            int u = tid + it * 256;          // 1024 x 16B units
            int row = u >> 3, q4 = u & 7;
            const __half* src = d_Gh + (size_t)(base + row) * G_DIM
                              + koff + S * SK + q4 * 8;
            cp_async16(au_base + (uint32_t)((buf * TM + row) * RPAD + q4 * 4) * 4u,
                       src);
        }
    };
    auto load2 = [&](int S, int p0, uint4* vi, uint4* vj) {   // PAIR only
        const size_t off = (size_t)(S * SK + q * 8);
        #pragma unroll
        for (int t = 0; t < 2; t++) {
            vi[t] = *reinterpret_cast<const uint4*>(
                d_Gh + (size_t)idx_i[p0 + t] * G_DIM + off);
            vj[t] = *reinterpret_cast<const uint4*>(
                d_Gh + (size_t)idx_j[p0 + t] * G_DIM + off);
        }
    };
    auto prod_sts2 = [&](int p0, const uint4* vi, const uint4* vj, int abuf) {
        #pragma unroll
        for (int t = 0; t < 2; t++) {
            __half2 a0 = *reinterpret_cast<const __half2*>(&vi[t].x);
            __half2 a1 = *reinterpret_cast<const __half2*>(&vi[t].y);
            __half2 a2 = *reinterpret_cast<const __half2*>(&vi[t].z);
            __half2 a3 = *reinterpret_cast<const __half2*>(&vi[t].w);
            __half2 b0 = *reinterpret_cast<const __half2*>(&vj[t].x);
            __half2 b1 = *reinterpret_cast<const __half2*>(&vj[t].y);
            __half2 b2v = *reinterpret_cast<const __half2*>(&vj[t].z);
            __half2 b3 = *reinterpret_cast<const __half2*>(&vj[t].w);
            __half2 p0h = __hmul2(a0, b0), p1h = __hmul2(a1, b1);
            __half2 p2h = __hmul2(a2, b2v), p3h = __hmul2(a3, b3);
            uint4 u;
            u.x = *reinterpret_cast<uint32_t*>(&p0h);
            u.y = *reinterpret_cast<uint32_t*>(&p1h);
            u.z = *reinterpret_cast<uint32_t*>(&p2h);
            u.w = *reinterpret_cast<uint32_t*>(&p3h);
            const int row = rbase + 32 * (p0 + t);
            *reinterpret_cast<uint4*>(Au + (size_t)(abuf * TM + row) * RPAD + q * 4) = u;
        }
    };
    auto mma_ks = [&](int abuf, int bbuf, int ks) {    // ks = 0..3
        uint32_t af[4][4];
        #pragma unroll
        for (int tm = 0; tm < 4; tm++) {
            uint32_t addr = a_lane_off
                + 4u * RPAD * (uint32_t)(abuf * TM + warp_m * 64 + tm * 16)
                + 32u * (uint32_t)ks;
            ldmatrix_x4(af[tm], addr);
        }
        #pragma unroll
        for (int tn = 0; tn < 5; tn++) {
            uint32_t addr = b_lane_off
                + 4u * RPAD * (uint32_t)(bbuf * TN + warp_n * 40 + tn * 8)
                + 32u * (uint32_t)ks;
            uint32_t bf[2];
            ldmatrix_x2(bf, addr);
            #pragma unroll
            for (int tm = 0; tm < 4; tm++)
                mma_f16(acc[tm][tn], af[tm], bf);
        }
    };

    if (PAIR) {
        // ---- prologue: commit B(0),B(1); gather A(0); retire B(0) ----
        stage_B(0, 0); CP_COMMIT();
        stage_B(1, 1); CP_COMMIT();
        {
            uint4 vi[2], vj[2];
            load2(0, 0, vi, vj);  prod_sts2(0, vi, vj, 0);
            load2(0, 2, vi, vj);  prod_sts2(2, vi, vj, 0);
        }
        CP_WAIT1();                  // B(0) retired; B(1) in flight
        __syncthreads();

        for (int S = 0; S < nsup; S++) {
            const int acur = S & 1, anxt = acur ^ 1;
            const int bcur = S % BBUFS;
            const bool more = (S + 1 < nsup);
            if (S + 2 < nsup) stage_B(S + 2, (S + 2) % BBUFS);
            CP_COMMIT();             // keep FIFO count (empty ok)
            uint4 vi0[2], vj0[2], vi1[2], vj1[2];
            if (more) load2(S + 1, 0, vi0, vj0);   // LDGs fly over MMA ks 0-1
            mma_ks(acur, bcur, 0);
            mma_ks(acur, bcur, 1);
            if (more) {
                prod_sts2(0, vi0, vj0, anxt);
                load2(S + 1, 2, vi1, vj1);         // LDGs fly over MMA ks 2-3
            }
            mma_ks(acur, bcur, 2);
            mma_ks(acur, bcur, 3);
            if (more) prod_sts2(2, vi1, vj1, anxt);
            CP_WAIT1();              // B(S+1) retired; B(S+2) in flight
            __syncthreads();         // A(S+1)+B(S+1) visible to all
        }
    } else {
        // ---- PRE: R12 scheme verbatim (double-buffered, WAIT0) ----
        stage_B(0, 0); stage_A_pre(0, 0); CP_COMMIT();
        CP_WAIT0();
        __syncthreads();
        for (int S = 0; S < nsup; S++) {
            const int cur = S & 1, nxt = cur ^ 1;
            const bool more = (S + 1 < nsup);
            if (more) { stage_B(S + 1, nxt); stage_A_pre(S + 1, nxt); }
            CP_COMMIT();
            mma_ks(cur, cur, 0);
            mma_ks(cur, cur, 1);
            mma_ks(cur, cur, 2);
            mma_ks(cur, cur, 3);
            CP_WAIT0();
            __syncthreads();
        }
    }

    // ---- epilogue ----
    if (PAIR) {
        #pragma unroll
        for (int tm = 0; tm < 4; tm++) {
            #pragma unroll
            for (int rh = 0; rh < 2; rh++) {
                const int lr = warp_m * 64 + tm * 16 + rh * 8 + gID;
                const int p = base + lr;
                const int ii = m_ids[p], jj = a_ids[p], sp = spk_lbl[p];
                const float* Ar = d_Abuf + (size_t)ii * TN;
                const float* Br = d_Bbuf + (size_t)jj * TN;
                const float* bi = bias_s + sp * TN;
                float part = 0.f;
                #pragma unroll
                for (int tn = 0; tn < 5; tn++) {
                    const int h = warp_n * 40 + tn * 8 + tig * 2;
                    float2 av = *reinterpret_cast<const float2*>(Ar + h);
                    float2 bv = *reinterpret_cast<const float2*>(Br + h);
                    float v0 = acc[tm][tn][rh * 2 + 0] + av.x + bv.x + bi[h];
                    float v1 = acc[tm][tn][rh * 2 + 1] + av.y + bv.y + bi[h + 1];
                    part = fmaf(fmaxf(v0, 0.f), w2s[h], part);
                    part = fmaf(fmaxf(v1, 0.f), w2s[h + 1], part);
                }
                part += __shfl_xor_sync(0xffffffffu, part, 1);
                part += __shfl_xor_sync(0xffffffffu, part, 2);
                if (tig == 0) srow[warp_n][lr] = part;
            }
        }
        __syncthreads();
        if (tid < TM) {
            const int p = base + tid;
            d_scores[p] = srow[0][tid] + srow[1][tid] + srow[2][tid] + srow[3][tid]
                        + b2[0] + mscores[m_ids[p]] + mscores[a_ids[p]];
        }
    } else {
        float* out = &d_part[blockIdx.z][blockIdx.y][0];
        #pragma unroll
        for (int tm = 0; tm < 4; tm++) {
            #pragma unroll
            for (int rh = 0; rh < 2; rh++) {
                const int m = base + warp_m * 64 + tm * 16 + rh * 8 + gID;
                #pragma unroll
                for (int tn = 0; tn < 5; tn++) {
                    const int h = warp_n * 40 + tn * 8 + tig * 2;
                    float2 v = make_float2(acc[tm][tn][rh * 2 + 0],
                                           acc[tm][tn][rh * 2 + 1]);
                    *reinterpret_cast<float2*>(out + (size_t)m * TN + h) = v;
                }
            }
        }
    }
}

// ---------------------------------------------------------------------------
__global__ void combine_kernel() {
    const int TOT = 2 * N_MENT * TN / 4;   // float4 units per split
    int qk = blockIdx.x * 256 + threadIdx.x;
    if (qk >= TOT) return;
    const float4* p = reinterpret_cast<const float4*>(d_part);
    float4 a = p[qk], b = p[qk + TOT], c = p[qk + 2 * TOT], d = p[qk + 3 * TOT];
    float4 r;
    r.x = a.x + b.x + c.x + d.x;
    r.y = a.y + b.y + c.y + d.y;
    r.z = a.z + b.z + c.z + d.z;
    r.w = a.w + b.w + c.w + d.w;
    const int HALF = TOT / 2;
    if (qk < HALF) reinterpret_cast<float4*>(d_Abuf)[qk] = r;
    else           reinterpret_cast<float4*>(d_Bbuf)[qk - HALF] = r;
}

// ---------------------------------------------------------------------------
__global__ void softmax_kernel(const int* __restrict__ seg_ids,
                               float* __restrict__ out) {
    const int s = (blockIdx.x * blockDim.x + threadIdx.x) >> 5;
    const int lane = threadIdx.x & 31;
    if (s >= N_SEG) return;

    int lo = 0, hi = N_PAIRS;
    while (lo < hi) { int mid = (lo + hi) >> 1; if (seg_ids[mid] < s) lo = mid + 1; else hi = mid; }
    const int start = lo;
    hi = N_PAIRS;
    while (lo < hi) { int mid = (lo + hi) >> 1; if (seg_ids[mid] <= s) lo = mid + 1; else hi = mid; }
    const int end = lo;

    float m = 0.f;
    for (int p = start + lane; p < end; p += 32) m = fmaxf(m, d_scores[p]);
    #pragma unroll
    for (int o = 16; o; o >>= 1) m = fmaxf(m, __shfl_xor_sync(0xffffffffu, m, o));

    float sum = 0.f;
    for (int p = start + lane; p < end; p += 32) sum += expf(d_scores[p] - m);
    #pragma unroll
    for (int o = 16; o; o >>= 1) sum += __shfl_xor_sync(0xffffffffu, sum, o);

    const float eps_e = expf(-m);
    const float inv = 1.f / (sum + eps_e);
    for (int p = start + lane; p < end; p += 32)
        out[p] = expf(d_scores[p] - m) * inv;
    if (lane == 0) out[N_PAIRS + s] = eps_e * inv;
}

// ---------------------------------------------------------------------------
extern "C" void kernel_launch(void* const* d_in, const int* in_sizes, int n_in,
                              void* d_out, int out_size) {
    const float* g_i            = (const float*)d_in[0];
    const float* mention_scores = (const float*)d_in[1];
    const float* speaker_embed  = (const float*)d_in[2];
    const float* W1             = (const float*)d_in[3];
    const float* b1             = (const float*)d_in[4];
    const float* W2             = (const float*)d_in[5];
    const float* b2             = (const float*)d_in[6];
    const int*   mention_ids    = (const int*)d_in[7];
    const int*   antecedent_ids = (const int*)d_in[8];
    const int*   speaker_labels = (const int*)d_in[9];
    const int*   segment_ids    = (const int*)d_in[10];
    float* out = (float*)d_out;

    cudaFuncSetAttribute(mma_kernel<false>,
                         cudaFuncAttributeMaxDynamicSharedMemorySize, DYN_BYTES);
    cudaFuncSetAttribute(mma_kernel<true>,
                         cudaFuncAttributeMaxDynamicSharedMemorySize, DYN_BYTES);

    prep_g_kernel<<<(N_MENT * G_DIM / 4 + 255) / 256, 256>>>(g_i);
    prep_w_kernel<<<dim3(G_DIM / 32, TN / 32, 3), dim3(32, 8)>>>(W1);
    bias_kernel<<<1, 256>>>(speaker_embed, W1, b1);
    // precompute: 32 M-tiles x 2 sections x 4 K-splits = 256 CTAs (full wave)
    mma_kernel<false><<<dim3(N_MENT / TM, 2, KSPLIT), 256, DYN_BYTES>>>(
        mention_ids, antecedent_ids, speaker_labels, mention_scores,
        W2, b2, NSUP_PRE);
    combine_kernel<<<(2 * N_MENT * TN / 4 + 255) / 256, 256>>>();
    // pair bilinear + fused epilogue: 256 CTAs
    mma_kernel<true><<<dim3(N_PAIRS / TM, 1, 1), 256, DYN_BYTES>>>(
        mention_ids, antecedent_ids, speaker_labels, mention_scores,
        W2, b2, NSUP);
    softmax_kernel<<<(N_SEG * 32 + 255) / 256, 256>>>(segment_ids, out);
}

// round 17
// speedup vs baseline: 1.2169x; 1.2169x over previous
#include <cuda_runtime.h>
#include <cuda_fp16.h>
#include <cstdint>
#include <math.h>

#define G_DIM   2304
#define HIDDEN  150
#define N_PAIRS 32768
#define N_MENT  4096
#define N_SEG   1024

#define TN 160
#define SK 64                    // K per stage
#define NSUP (G_DIM / SK)        // 36

#define RPAD 36    // uint row stride (32 data + 4 pad), conflict-free

#define AS_UINTS (2 * 128 * RPAD)          // 9216  (sized for pair TM=128)
#define BS_UINTS (2 * TN * RPAD)           // 11520
#define DYN_BYTES ((AS_UINTS + BS_UINTS) * 4)   // 82944

// ---------------- device scratch (static; no allocation) -------------------
__device__ __half d_Gh[N_MENT * G_DIM];           // g_i in fp16
__device__ __half d_Wh[3 * TN * G_DIM];           // W1^T fp16 [sec][h][k]
__device__ float d_Abuf[N_MENT * TN];
__device__ float d_Bbuf[N_MENT * TN];
__device__ float d_bias[3 * TN];
__device__ float d_scores[N_PAIRS];

__device__ __forceinline__ uint32_t smem_u32(const void* p) {
    uint32_t a;
    asm("{ .reg .u64 t; cvta.to.shared.u64 t, %1; cvt.u32.u64 %0, t; }"
        : "=r"(a) : "l"(p));
    return a;
}
__device__ __forceinline__ void cp_async16(uint32_t dst, const void* src) {
    asm volatile("cp.async.cg.shared.global [%0], [%1], 16;"
                 :: "r"(dst), "l"(src) : "memory");
}
#define CP_COMMIT() asm volatile("cp.async.commit_group;" ::: "memory")
#define CP_WAIT0()  asm volatile("cp.async.wait_group 0;" ::: "memory")

__device__ __forceinline__ void mma_f16(float* d, const uint32_t* a,
                                        const uint32_t* b) {
    asm volatile(
        "mma.sync.aligned.m16n8k16.row.col.f32.f16.f16.f32 "
        "{%0,%1,%2,%3}, {%4,%5,%6,%7}, {%8,%9}, {%0,%1,%2,%3};"
        : "+f"(d[0]), "+f"(d[1]), "+f"(d[2]), "+f"(d[3])
        : "r"(a[0]), "r"(a[1]), "r"(a[2]), "r"(a[3]), "r"(b[0]), "r"(b[1]));
}
__device__ __forceinline__ void ldmatrix_x4(uint32_t* r, uint32_t addr) {
    asm volatile("ldmatrix.sync.aligned.m8n8.x4.shared.b16 {%0,%1,%2,%3}, [%4];"
                 : "=r"(r[0]), "=r"(r[1]), "=r"(r[2]), "=r"(r[3]) : "r"(addr));
}
__device__ __forceinline__ void ldmatrix_x2(uint32_t* r, uint32_t addr) {
    asm volatile("ldmatrix.sync.aligned.m8n8.x2.shared.b16 {%0,%1}, [%2];"
                 : "=r"(r[0]), "=r"(r[1]) : "r"(addr));
}

// ---------------------------------------------------------------------------
__global__ void prep_g_kernel(const float* __restrict__ G) {
    int idx = blockIdx.x * 256 + threadIdx.x;     // float4 units
    if (idx >= N_MENT * G_DIM / 4) return;
    float4 v = reinterpret_cast<const float4*>(G)[idx];
    __half2 h0 = __floats2half2_rn(v.x, v.y);
    __half2 h1 = __floats2half2_rn(v.z, v.w);
    uint2 u;
    u.x = *reinterpret_cast<uint32_t*>(&h0);
    u.y = *reinterpret_cast<uint32_t*>(&h1);
    reinterpret_cast<uint2*>(d_Gh)[idx] = u;
}

// ---------------------------------------------------------------------------
__global__ void prep_w_kernel(const float* __restrict__ W1) {
    __shared__ float t[32][33];
    const int k0 = blockIdx.x * 32, h0 = blockIdx.y * 32, sec = blockIdx.z;
    const int tx = threadIdx.x, ty = threadIdx.y;
    #pragma unroll
    for (int r = 0; r < 4; r++) {
        int ky = ty + r * 8, h = h0 + tx;
        t[ky][tx] = (h < HIDDEN)
            ? W1[(size_t)(sec * G_DIM + k0 + ky) * HIDDEN + h] : 0.f;
    }
    __syncthreads();
    #pragma unroll
    for (int r = 0; r < 4; r++) {
        int hy = ty + r * 8;
        d_Wh[(size_t)sec * TN * G_DIM + (size_t)(h0 + hy) * G_DIM + k0 + tx] =
            __float2half_rn(t[tx][hy]);
    }
}

// ---------------------------------------------------------------------------
__global__ void bias_kernel(const float* __restrict__ spk,
                            const float* __restrict__ W1,
                            const float* __restrict__ b1) {
    const float* Wd = W1 + (size_t)(3 * G_DIM) * HIDDEN;
    for (int idx = threadIdx.x; idx < 3 * TN; idx += blockDim.x) {
        int s = idx / TN, h = idx % TN;
        float v = 0.f;
        if (h < HIDDEN) {
            v = b1[h];
            #pragma unroll
            for (int t = 0; t < 20; t++)
                v = fmaf(spk[s * 20 + t], Wd[(size_t)t * HIDDEN + h], v);
        }
        d_bias[idx] = v;
    }
}

// ---------------------------------------------------------------------------
// fp16 mma.sync GEMM (m16n8k16), ldmatrix frags (B packed x4), SK=64 stages,
// A+B double-buffered, WAIT0 + ONE barrier per stage (R12 pipeline).
// 8 warps (2 M x 4 N).
//   PAIR=true : TM=128 (MT=4), A = hmul2 gather; full K -> d_scores
//   PAIR=false: TM=64  (MT=2), A pure cp.async; full K -> d_Abuf/d_Bbuf direct
// ---------------------------------------------------------------------------
template<bool PAIR>
__global__ __launch_bounds__(256, 2)
void mma_kernel(const int*   __restrict__ m_ids,
                const int*   __restrict__ a_ids,
                const int*   __restrict__ spk_lbl,
                const float* __restrict__ mscores,
                const float* __restrict__ W2,
                const float* __restrict__ b2) {
    constexpr int MT = PAIR ? 4 : 2;       // m16 tiles per warp
    constexpr int TM = MT * 32;            // 128 / 64

    extern __shared__ uint32_t dynu[];
    uint32_t* Au = dynu;                   // [2][TM][RPAD]
    uint32_t* Bu = dynu + AS_UINTS;        // [2][TN][RPAD]
    __shared__ float srow[4][128];
    __shared__ float bias_s[3 * TN];
    __shared__ float w2s[TN];

    const int tid = threadIdx.x;
    const int wid = tid >> 5, lane = tid & 31;
    const int gID = lane >> 2, tig = lane & 3;
    const int warp_m = wid & 1, warp_n = wid >> 1;
    const int base = blockIdx.x * TM;

    if (PAIR) {
        if (tid < TN) w2s[tid] = (tid < HIDDEN) ? W2[tid] : 0.f;
        for (int i = tid; i < 3 * TN; i += 256) bias_s[i] = d_bias[i];
    }

    const __half* Wh = d_Wh + (size_t)(PAIR ? 2 : blockIdx.y) * TN * G_DIM;

    // A-gather roles (PAIR): 8 threads/row, q = 16B slot; MT row passes.
    const int rbase = tid >> 3;   // 0..31
    const int q = tid & 7;        // 0..7
    int idx_i[4], idx_j[4];
    if (PAIR) {
        #pragma unroll
        for (int p = 0; p < 4; p++) {
            const int r = base + rbase + 32 * p;
            idx_i[p] = m_ids[r];
            idx_j[p] = a_ids[r];
        }
    }

    float acc[MT][5][4];
    #pragma unroll
    for (int a = 0; a < MT; a++)
        #pragma unroll
        for (int b = 0; b < 5; b++)
            #pragma unroll
            for (int c = 0; c < 4; c++) acc[a][b][c] = 0.f;

    const uint32_t au_base = smem_u32(Au);
    const uint32_t bs_base = smem_u32(Bu);

    // ldmatrix lane addressing (bytes)
    const int a_rowsel = (lane & 7) + ((lane >> 3) & 1) * 8;
    const int a_ksel   = (lane >> 4) & 1;
    const uint32_t a_lane_off = au_base
        + 4u * ((uint32_t)a_rowsel * RPAD + (uint32_t)a_ksel * 4);
    const int b_colsel = lane & 7;
    const int b_ksel   = (lane >> 3) & 1;
    // x2 (single n8 tile):
    const uint32_t b2_lane_off = bs_base
        + 4u * ((uint32_t)b_colsel * RPAD + (uint32_t)b_ksel * 4);
    // x4 (two n8 tiles: lanes 16-31 -> cols +8):
    const uint32_t b4_lane_off = bs_base
        + 4u * ((uint32_t)(b_colsel + ((lane >> 4) & 1) * 8) * RPAD
                + (uint32_t)b_ksel * 4);

    auto stage_B = [&](int S, int buf) {
        #pragma unroll
        for (int it = 0; it < 5; it++) {
            int u = tid + it * 256;          // 1280 x 16B units
            int col = u >> 3, q4 = u & 7;
            const __half* src = Wh + (size_t)col * G_DIM + S * SK + q4 * 8;
            cp_async16(bs_base + (uint32_t)((buf * TN + col) * RPAD + q4 * 4) * 4u,
                       src);
        }
    };
    auto stage_A_pre = [&](int S, int buf) {   // PRE only: TM=64 rows
        #pragma unroll
        for (int it = 0; it < 2; it++) {
            int u = tid + it * 256;          // 512 x 16B units
            int row = u >> 3, q4 = u & 7;
            const __half* src = d_Gh + (size_t)(base + row) * G_DIM
                              + S * SK + q4 * 8;
            cp_async16(au_base + (uint32_t)((buf * TM + row) * RPAD + q4 * 4) * 4u,
                       src);
        }
    };
    auto load2 = [&](int S, int p0, uint4* vi, uint4* vj) {   // PAIR only
        const size_t off = (size_t)(S * SK + q * 8);
        #pragma unroll
        for (int t = 0; t < 2; t++) {
            vi[t] = *reinterpret_cast<const uint4*>(
                d_Gh + (size_t)idx_i[p0 + t] * G_DIM + off);
            vj[t] = *reinterpret_cast<const uint4*>(
                d_Gh + (size_t)idx_j[p0 + t] * G_DIM + off);
        }
    };
    auto prod_sts2 = [&](int p0, const uint4* vi, const uint4* vj, int abuf) {
        #pragma unroll
        for (int t = 0; t < 2; t++) {
            __half2 a0 = *reinterpret_cast<const __half2*>(&vi[t].x);
            __half2 a1 = *reinterpret_cast<const __half2*>(&vi[t].y);
            __half2 a2 = *reinterpret_cast<const __half2*>(&vi[t].z);
            __half2 a3 = *reinterpret_cast<const __half2*>(&vi[t].w);
            __half2 b0 = *reinterpret_cast<const __half2*>(&vj[t].x);
            __half2 b1 = *reinterpret_cast<const __half2*>(&vj[t].y);
            __half2 b2v = *reinterpret_cast<const __half2*>(&vj[t].z);
            __half2 b3 = *reinterpret_cast<const __half2*>(&vj[t].w);
            __half2 p0h = __hmul2(a0, b0), p1h = __hmul2(a1, b1);
            __half2 p2h = __hmul2(a2, b2v), p3h = __hmul2(a3, b3);
            uint4 u;
            u.x = *reinterpret_cast<uint32_t*>(&p0h);
            u.y = *reinterpret_cast<uint32_t*>(&p1h);
            u.z = *reinterpret_cast<uint32_t*>(&p2h);
            u.w = *reinterpret_cast<uint32_t*>(&p3h);
            const int row = rbase + 32 * (p0 + t);
            *reinterpret_cast<uint4*>(Au + (size_t)(abuf * TM + row) * RPAD + q * 4) = u;
        }
    };
    auto mma_ks = [&](int buf, int ks) {       // ks = 0..3
        uint32_t af[MT][4];
        #pragma unroll
        for (int tm = 0; tm < MT; tm++) {
            uint32_t addr = a_lane_off
                + 4u * RPAD * (uint32_t)(buf * TM + warp_m * (MT * 16) + tm * 16)
                + 32u * (uint32_t)ks;
            ldmatrix_x4(af[tm], addr);
        }
        // B: 2 x ldmatrix_x4 (tn pairs 0-1, 2-3) + 1 x ldmatrix_x2 (tn 4)
        #pragma unroll
        for (int tp = 0; tp < 2; tp++) {
            uint32_t addr = b4_lane_off
                + 4u * RPAD * (uint32_t)(buf * TN + warp_n * 40 + tp * 16)
                + 32u * (uint32_t)ks;
            uint32_t bf[4];
            ldmatrix_x4(bf, addr);
            #pragma unroll
            for (int tm = 0; tm < MT; tm++) {
                mma_f16(acc[tm][tp * 2 + 0], af[tm], bf);
                mma_f16(acc[tm][tp * 2 + 1], af[tm], bf + 2);
            }
        }
        {
            uint32_t addr = b2_lane_off
                + 4u * RPAD * (uint32_t)(buf * TN + warp_n * 40 + 32)
                + 32u * (uint32_t)ks;
            uint32_t bf[2];
            ldmatrix_x2(bf, addr);
            #pragma unroll
            for (int tm = 0; tm < MT; tm++)
                mma_f16(acc[tm][4], af[tm], bf);
        }
    };

    // ---- prologue: stage S=0 into buffer 0 (R12 scheme) ----
    if (PAIR) {
        stage_B(0, 0);
        CP_COMMIT();
        uint4 vi[2], vj[2];
        load2(0, 0, vi, vj);  prod_sts2(0, vi, vj, 0);
        load2(0, 2, vi, vj);  prod_sts2(2, vi, vj, 0);
        CP_WAIT0();
        __syncthreads();
    } else {
        stage_B(0, 0);
        stage_A_pre(0, 0);
        CP_COMMIT();
        CP_WAIT0();
        __syncthreads();
    }

    for (int S = 0; S < NSUP; S++) {
        const int cur = S & 1, nxt = cur ^ 1;
        const bool more = (S + 1 < NSUP);
        if (PAIR) {
            if (more) stage_B(S + 1, nxt);
            CP_COMMIT();
            uint4 vi[2], vj[2];
            if (more) load2(S + 1, 0, vi, vj);  // LDGs fly over MMA ks 0-1
            mma_ks(cur, 0);
            mma_ks(cur, 1);
            if (more) {
                prod_sts2(0, vi, vj, nxt);
                load2(S + 1, 2, vi, vj);        // LDGs fly over MMA ks 2-3
            }
            mma_ks(cur, 2);
            mma_ks(cur, 3);
            if (more) prod_sts2(2, vi, vj, nxt);
        } else {
            if (more) { stage_B(S + 1, nxt); stage_A_pre(S + 1, nxt); }
            CP_COMMIT();
            mma_ks(cur, 0);
            mma_ks(cur, 1);
            mma_ks(cur, 2);
            mma_ks(cur, 3);
        }
        CP_WAIT0();
        __syncthreads();                     // single barrier per stage
    }

    // ---- epilogue ----
    if (PAIR) {
        #pragma unroll
        for (int tm = 0; tm < MT; tm++) {
            #pragma unroll
            for (int rh = 0; rh < 2; rh++) {
                const int lr = warp_m * (MT * 16) + tm * 16 + rh * 8 + gID;
                const int p = base + lr;
                const int ii = m_ids[p], jj = a_ids[p], sp = spk_lbl[p];
                const float* Ar = d_Abuf + (size_t)ii * TN;
                const float* Br = d_Bbuf + (size_t)jj * TN;
                const float* bi = bias_s + sp * TN;
                float part = 0.f;
                #pragma unroll
                for (int tn = 0; tn < 5; tn++) {
                    const int h = warp_n * 40 + tn * 8 + tig * 2;
                    float2 av = *reinterpret_cast<const float2*>(Ar + h);
                    float2 bv = *reinterpret_cast<const float2*>(Br + h);
                    float v0 = acc[tm][tn][rh * 2 + 0] + av.x + bv.x + bi[h];
                    float v1 = acc[tm][tn][rh * 2 + 1] + av.y + bv.y + bi[h + 1];
                    part = fmaf(fmaxf(v0, 0.f), w2s[h], part);
                    part = fmaf(fmaxf(v1, 0.f), w2s[h + 1], part);
                }
                part += __shfl_xor_sync(0xffffffffu, part, 1);
                part += __shfl_xor_sync(0xffffffffu, part, 2);
                if (tig == 0) srow[warp_n][lr] = part;
            }
        }
        __syncthreads();
        if (tid < TM) {
            const int p = base + tid;
            d_scores[p] = srow[0][tid] + srow[1][tid] + srow[2][tid] + srow[3][tid]
                        + b2[0] + mscores[m_ids[p]] + mscores[a_ids[p]];
        }
    } else {
        float* out = (blockIdx.y == 0) ? d_Abuf : d_Bbuf;
        #pragma unroll
        for (int tm = 0; tm < MT; tm++) {
            #pragma unroll
            for (int rh = 0; rh < 2; rh++) {
                const int m = base + warp_m * (MT * 16) + tm * 16 + rh * 8 + gID;
                #pragma unroll
                for (int tn = 0; tn < 5; tn++) {
                    const int h = warp_n * 40 + tn * 8 + tig * 2;
                    float2 v = make_float2(acc[tm][tn][rh * 2 + 0],
                                           acc[tm][tn][rh * 2 + 1]);
                    *reinterpret_cast<float2*>(out + (size_t)m * TN + h) = v;
                }
            }
        }
    }
}

// ---------------------------------------------------------------------------
__global__ void softmax_kernel(const int* __restrict__ seg_ids,
                               float* __restrict__ out) {
    const int s = (blockIdx.x * blockDim.x + threadIdx.x) >> 5;
    const int lane = threadIdx.x & 31;
    if (s >= N_SEG) return;

    int lo = 0, hi = N_PAIRS;
    while (lo < hi) { int mid = (lo + hi) >> 1; if (seg_ids[mid] < s) lo = mid + 1; else hi = mid; }
    const int start = lo;
    hi = N_PAIRS;
    while (lo < hi) { int mid = (lo + hi) >> 1; if (seg_ids[mid] <= s) lo = mid + 1; else hi = mid; }
    const int end = lo;

    float m = 0.f;
    for (int p = start + lane; p < end; p += 32) m = fmaxf(m, d_scores[p]);
    #pragma unroll
    for (int o = 16; o; o >>= 1) m = fmaxf(m, __shfl_xor_sync(0xffffffffu, m, o));

    float sum = 0.f;
    for (int p = start + lane; p < end; p += 32) sum += expf(d_scores[p] - m);
    #pragma unroll
    for (int o = 16; o; o >>= 1) sum += __shfl_xor_sync(0xffffffffu, sum, o);

    const float eps_e = expf(-m);
    const float inv = 1.f / (sum + eps_e);
    for (int p = start + lane; p < end; p += 32)
        out[p] = expf(d_scores[p] - m) * inv;
    if (lane == 0) out[N_PAIRS + s] = eps_e * inv;
}

// ---------------------------------------------------------------------------
extern "C" void kernel_launch(void* const* d_in, const int* in_sizes, int n_in,
                              void* d_out, int out_size) {
    const float* g_i            = (const float*)d_in[0];
    const float* mention_scores = (const float*)d_in[1];
    const float* speaker_embed  = (const float*)d_in[2];
    const float* W1             = (const float*)d_in[3];
    const float* b1             = (const float*)d_in[4];
    const float* W2             = (const float*)d_in[5];
    const float* b2             = (const float*)d_in[6];
    const int*   mention_ids    = (const int*)d_in[7];
    const int*   antecedent_ids = (const int*)d_in[8];
    const int*   speaker_labels = (const int*)d_in[9];
    const int*   segment_ids    = (const int*)d_in[10];
    float* out = (float*)d_out;

    cudaFuncSetAttribute(mma_kernel<false>,
                         cudaFuncAttributeMaxDynamicSharedMemorySize, DYN_BYTES);
    cudaFuncSetAttribute(mma_kernel<true>,
                         cudaFuncAttributeMaxDynamicSharedMemorySize, DYN_BYTES);

    prep_g_kernel<<<(N_MENT * G_DIM / 4 + 255) / 256, 256>>>(g_i);
    prep_w_kernel<<<dim3(G_DIM / 32, TN / 32, 3), dim3(32, 8)>>>(W1);
    bias_kernel<<<1, 256>>>(speaker_embed, W1, b1);
    // precompute: TM=64, full K, direct write -> 64 M-tiles x 2 sections
    mma_kernel<false><<<dim3(N_MENT / 64, 2), 256, DYN_BYTES>>>(
        mention_ids, antecedent_ids, speaker_labels, mention_scores, W2, b2);
    // pair bilinear + fused epilogue: 256 CTAs
    mma_kernel<true><<<dim3(N_PAIRS / 128, 1), 256, DYN_BYTES>>>(
        mention_ids, antecedent_ids, speaker_labels, mention_scores, W2, b2);
    softmax_kernel<<<(N_SEG * 32 + 255) / 256, 256>>>(segment_ids, out);
}